// round 3
// baseline (speedup 1.0000x reference)
#include <cuda_runtime.h>

// HausdorffDTLoss, [4,1,256,256] fp32 inputs.
// loss = mean( (pred-target)^2 * (pred_dt^2 + target_dt^2) )
// dt^2 = min(F_fg,BIG) + min(F_~fg,BIG)  (exactly one EDT is 0 per pixel),
// F = separable 1D min-plus squared-distance transform (y-pass then x-pass),
// with a warp-uniform batched early-exit window (bit-exact vs brute force:
// every evaluated candidate is the identical fp32 expression f[j]+(i-j)^2,
// and extra candidates can never beat the true min since f >= 0).
//
// Loss separability: sum e*(dp+dt) = sum e*dp + sum e*dt, so stage2 blocks
// handle ONE image each (2x parallelism, half the serial scans per thread).

#define BIGF 1e10f
#define HW 256
#define IMG 65536
#define TOTAL 262144
#define STRIDE 768        // 256 left pad | 256 data | 256 right pad

// Vertical-pass output, layout [in(2)][b(4)][mask(2)][x][y] (transposed)
__device__ float g_P1[2 * 4 * 2 * IMG];
__device__ int g_fgany[8];          // [in*4 + b]; zero-init, self-reset
__device__ double g_accum;          // zero-init, self-reset
__device__ unsigned int g_counter;  // zero-init, self-reset

// Fused windowed min-plus scan over two arrays sharing one window.
// F, N point at element 0 of 256 valid entries with >=256 BIG pads each side.
__device__ __forceinline__ void scan2(const float* __restrict__ F,
                                      const float* __restrict__ N,
                                      int i, float& outF, float& outN)
{
    float mF = F[i];
    float mN = N[i];
    float d2 = 1.0f, st = 3.0f;      // d2 = d*d, st = 2d+1
    #pragma unroll 1
    for (int d = 1; d <= 253; d += 4) {          // covers d = 1..256
        if (__all_sync(0xFFFFFFFFu, d2 >= mF && d2 >= mN)) break;
        #pragma unroll
        for (int u = 0; u < 4; ++u) {
            int dd = d + u;
            mF = fminf(mF, fminf(F[i - dd], F[i + dd]) + d2);
            mN = fminf(mN, fminf(N[i - dd], N[i + dd]) + d2);
            d2 += st; st += 2.0f;
        }
    }
    outF = mF; outN = mN;
}

// ---------------------------------------------------------------------------
// Stage 1: vertical min-plus (along y). Block = (in, b, 4-column tile).
// 512 blocks, 256 threads (one per y). Output transposed [x][y].
// ---------------------------------------------------------------------------
__global__ __launch_bounds__(256) void stage1_kernel(
    const float* __restrict__ pred, const float* __restrict__ target)
{
    __shared__ __align__(16) float s[8 * STRIDE];  // rows 0-3: fg, 4-7: ~fg

    int bid = blockIdx.x;            // 0..511
    int xt  = bid & 63;
    int b   = (bid >> 6) & 3;
    int in  = bid >> 8;
    int x0  = xt * 4;
    int tid = threadIdx.x;

    #pragma unroll
    for (int r = 0; r < 8; ++r) {    // pads only
        s[r * STRIDE + tid]       = BIGF;
        s[r * STRIDE + 512 + tid] = BIGF;
    }

    const float* img = (in == 0 ? pred : target) + b * IMG;

    int anyfg = 0;
    #pragma unroll
    for (int it = 0; it < 4; ++it) {
        int idx = it * 256 + tid;
        int j = idx >> 2;            // y
        int k = idx & 3;             // column within tile
        float v = img[j * HW + x0 + k];
        bool fg = v > 0.5f;
        anyfg |= (int)fg;
        s[k * STRIDE + 256 + j]       = fg ? BIGF : 0.0f;
        s[(4 + k) * STRIDE + 256 + j] = fg ? 0.0f : BIGF;
    }
    int blk_any = __syncthreads_or(anyfg);
    if (tid == 0 && blk_any) atomicOr(&g_fgany[in * 4 + b], 1);

    int y = tid;
    #pragma unroll 1
    for (int k = 0; k < 4; ++k) {
        float mF, mN;
        scan2(s + k * STRIDE + 256, s + (4 + k) * STRIDE + 256, y, mF, mN);
        int base = ((in * 4 + b) * 2) * IMG + (x0 + k) * HW + y;
        g_P1[base]       = mF;       // coalesced across threads (y)
        g_P1[base + IMG] = mN;
    }
}

// ---------------------------------------------------------------------------
// Stage 2: horizontal min-plus + per-image loss term + reduction + finalize.
// Block = (in, b, 4-row tile). 512 blocks, 256 threads (one per x).
// ---------------------------------------------------------------------------
__global__ __launch_bounds__(256) void stage2_kernel(
    const float* __restrict__ pred, const float* __restrict__ target,
    float* __restrict__ out)
{
    __shared__ __align__(16) float s[8 * STRIDE];

    int bid = blockIdx.x;
    int yt  = bid & 63;
    int b   = (bid >> 6) & 3;
    int in  = bid >> 8;
    int y0  = yt * 4;
    int tid = threadIdx.x;

    #pragma unroll
    for (int r = 0; r < 8; ++r) {
        s[r * STRIDE + tid]       = BIGF;
        s[r * STRIDE + 512 + tid] = BIGF;
    }

    const float* P0 = g_P1 + ((in * 4 + b) * 2) * IMG;   // [x][y] layout
    #pragma unroll
    for (int m = 0; m < 2; ++m) {
        const float* P = P0 + m * IMG;
        #pragma unroll
        for (int it = 0; it < 4; ++it) {
            int idx = it * 256 + tid;
            int j = idx >> 2;        // x
            int k = idx & 3;         // row within tile
            s[(m * 4 + k) * STRIDE + 256 + j] = P[j * HW + y0 + k];
        }
    }
    __syncthreads();

    int x = tid;
    int fg = g_fgany[in * 4 + b];
    const float* pr = pred + b * IMG;
    const float* tg = target + b * IMG;

    double acc = 0.0;
    #pragma unroll 1
    for (int k = 0; k < 4; ++k) {
        float mF, mN;
        scan2(s + k * STRIDE + 256, s + (4 + k) * STRIDE + 256, x, mF, mN);
        float dv = fminf(mF, BIGF) + fminf(mN, BIGF);   // this image's dt^2
        float p = pr[(y0 + k) * HW + x];
        float t = tg[(y0 + k) * HW + x];
        float e = (p - t) * (p - t);
        acc += (double)e * (double)dv;
    }
    if (!fg) acc = 0.0;              // empty-foreground image contributes 0

    // Block reduction: warp shuffles, then smem (reused) for 8 warp sums.
    #pragma unroll
    for (int o = 16; o > 0; o >>= 1)
        acc += __shfl_down_sync(0xFFFFFFFFu, acc, o);

    __syncthreads();                 // done reading s; safe to reuse
    double* ws = (double*)s;
    int wid = tid >> 5, lane = tid & 31;
    if (lane == 0) ws[wid] = acc;
    __syncthreads();

    if (tid == 0) {
        double bsum = 0.0;
        #pragma unroll
        for (int w = 0; w < 8; ++w) bsum += ws[w];
        atomicAdd(&g_accum, bsum);
        __threadfence();
        unsigned done = atomicAdd(&g_counter, 1u);
        if (done == gridDim.x - 1) {
            double tot = atomicAdd(&g_accum, 0.0);     // coherent read
            out[0] = (float)(tot * (1.0 / (double)TOTAL));
            // Self-reset device state for the next graph replay.
            g_accum = 0.0;
            g_counter = 0u;
            #pragma unroll
            for (int i = 0; i < 8; ++i) g_fgany[i] = 0;
        }
    }
}

extern "C" void kernel_launch(void* const* d_in, const int* in_sizes, int n_in,
                              void* d_out, int out_size) {
    const float* pred   = (const float*)d_in[0];
    const float* target = (const float*)d_in[1];
    float* out = (float*)d_out;

    stage1_kernel<<<512, 256>>>(pred, target);
    stage2_kernel<<<512, 256>>>(pred, target, out);
}

// round 4
// speedup vs baseline: 1.3596x; 1.3596x over previous
#include <cuda_runtime.h>

// HausdorffDTLoss, [4,1,256,256] fp32 inputs.
// loss = mean( (pred-target)^2 * (pred_dt^2 + target_dt^2) )
// dt^2 = min(F_fg,BIG) + min(F_~fg,BIG)  (exactly one EDT is 0 per pixel),
// F = separable 1D min-plus squared-distance transform (y-pass then x-pass),
// each 1D transform computed as an outward windowed scan with per-lane early
// exit (bit-exact vs brute force: every evaluated candidate is the identical
// fp32 expression f[j] + (i-j)^2, and since f >= 0 any candidate at distance
// d with d^2 >= current-min cannot win).
//
// fg and ~fg are scanned SEPARATELY (one is ~0 at every pixel -> its window
// is ~0 steps; joint scanning would run both to the max of the two windows).
// Loss separability: sum e*(dp+dt) = sum e*dp + sum e*dt -> stage2 blocks
// handle one image each.

#define BIGF 1e10f
#define HW 256
#define IMG 65536
#define TOTAL 262144
#define ARR 766          // array stride in floats (766 % 32 = 30 -> distinct banks)
#define OFF 255          // data starts at 255 (255 pad left, 255 pad right)

// Vertical-pass output, layout [in(2)][b(4)][mask(2)][x][y] (transposed)
__device__ float g_P1[2 * 4 * 2 * IMG];
__device__ int g_fgany[8];          // [in*4 + b]; zero-init, self-reset
__device__ double g_accum;          // zero-init, self-reset
__device__ unsigned int g_counter;  // zero-init, self-reset

// Windowed min-plus scan over ONE array. A points at element 0 of 256 valid
// entries with 255 BIG pads on each side. Per-lane early exit.
__device__ __forceinline__ float scan1(const float* __restrict__ A, int i)
{
    float m = A[i];
    float d2 = 1.0f, st = 3.0f;      // d2 = d*d, st = 2d+1 (exact in fp32)
    #pragma unroll 1
    for (int d = 1; d < 256; ++d) {
        if (d2 >= m) break;          // no farther candidate can win
        m = fminf(m, fminf(A[i - d], A[i + d]) + d2);
        d2 += st; st += 2.0f;
    }
    return m;
}

// ---------------------------------------------------------------------------
// Stage 1: vertical min-plus (along y). Block = (in, b, 8-column tile).
// 256 blocks x 1024 threads; 16 arrays (8 cols x 2 masks); 4 scans/thread.
// Output transposed [x][y] so stage-2 loads are coalesced.
// ---------------------------------------------------------------------------
__global__ __launch_bounds__(1024) void stage1_kernel(
    const float* __restrict__ pred, const float* __restrict__ target)
{
    __shared__ __align__(16) float s[16 * ARR];   // 49024 B

    int bid = blockIdx.x;            // 0..255
    int xt  = bid & 31;
    int b   = (bid >> 5) & 3;
    int in  = bid >> 7;
    int x0  = xt * 8;
    int tid = threadIdx.x;

    // Fill everything with BIG (covers pads), then overwrite the data region.
    #pragma unroll
    for (int it = 0; it < 12; ++it) {
        int idx = it * 1024 + tid;
        if (idx < 16 * ARR) s[idx] = BIGF;
    }
    __syncthreads();

    const float* img = (in == 0 ? pred : target) + b * IMG;

    int anyfg = 0;
    #pragma unroll
    for (int it = 0; it < 2; ++it) {
        int idx = it * 1024 + tid;
        int j = idx >> 3;            // y
        int k = idx & 7;             // column within tile
        float v = img[j * HW + x0 + k];        // coalesced
        bool fg = v > 0.5f;
        anyfg |= (int)fg;
        // array a = k*2 + mask; banks (30a + j) % 32 -> conflict-free
        s[(k * 2 + 0) * ARR + OFF + j] = fg ? BIGF : 0.0f;
        s[(k * 2 + 1) * ARR + OFF + j] = fg ? 0.0f : BIGF;
    }
    int blk_any = __syncthreads_or(anyfg);
    if (tid == 0 && blk_any) atomicOr(&g_fgany[in * 4 + b], 1);

    // 4 scans per thread: site = it*1024 + tid; a = site>>8 (0..15), y = site&255.
    float res[4];
    #pragma unroll
    for (int it = 0; it < 4; ++it) {
        int site = it * 1024 + tid;
        res[it] = scan1(s + (site >> 8) * ARR + OFF, site & 255);
    }
    int base = ((in * 4 + b) * 2) * IMG;
    #pragma unroll
    for (int it = 0; it < 4; ++it) {
        int site = it * 1024 + tid;
        int y = site & 255;
        int a = site >> 8;
        int k = a >> 1, m = a & 1;
        g_P1[base + m * IMG + (x0 + k) * HW + y] = res[it];   // coalesced (y fast)
    }
}

// ---------------------------------------------------------------------------
// Stage 2: horizontal min-plus + per-image loss + reduction + finalize.
// Block = (in, b, 8-row tile). 256 blocks x 1024 threads; 4 scans/thread.
// ---------------------------------------------------------------------------
__global__ __launch_bounds__(1024) void stage2_kernel(
    const float* __restrict__ pred, const float* __restrict__ target,
    float* __restrict__ out)
{
    __shared__ __align__(16) float s[16 * ARR];

    int bid = blockIdx.x;
    int yt  = bid & 31;
    int b   = (bid >> 5) & 3;
    int in  = bid >> 7;
    int y0  = yt * 8;
    int tid = threadIdx.x;

    #pragma unroll
    for (int it = 0; it < 12; ++it) {
        int idx = it * 1024 + tid;
        if (idx < 16 * ARR) s[idx] = BIGF;
    }
    __syncthreads();

    // Load 2 masks x 8 rows x 256 x from transposed P1 (coalesced: r fast).
    const float* P0 = g_P1 + ((in * 4 + b) * 2) * IMG;   // [x][y] layout
    #pragma unroll
    for (int mm = 0; mm < 2; ++mm) {
        const float* P = P0 + mm * IMG;
        #pragma unroll
        for (int it = 0; it < 2; ++it) {
            int idx = it * 1024 + tid;
            int x = idx >> 3;        // x
            int r = idx & 7;         // row within tile
            s[(r * 2 + mm) * ARR + OFF + x] = P[x * HW + y0 + r];
        }
    }
    __syncthreads();

    // 4 scans per thread -> registers.
    float res[4];
    #pragma unroll
    for (int it = 0; it < 4; ++it) {
        int site = it * 1024 + tid;
        res[it] = scan1(s + (site >> 8) * ARR + OFF, site & 255);
    }
    __syncthreads();                 // all scans done reading s

    // Write results back into s (same slots), then combine.
    #pragma unroll
    for (int it = 0; it < 4; ++it) {
        int site = it * 1024 + tid;
        s[(site >> 8) * ARR + OFF + (site & 255)] = res[it];
    }
    __syncthreads();

    int fg = g_fgany[in * 4 + b];
    const float* pr = pred + b * IMG;
    const float* tg = target + b * IMG;

    double acc = 0.0;
    #pragma unroll
    for (int it = 0; it < 2; ++it) {
        int idx = it * 1024 + tid;
        int r = idx >> 8;            // row within tile
        int x = idx & 255;
        float mF = s[(r * 2 + 0) * ARR + OFF + x];
        float mN = s[(r * 2 + 1) * ARR + OFF + x];
        float dv = fminf(mF, BIGF) + fminf(mN, BIGF);   // this image's dt^2
        float p = pr[(y0 + r) * HW + x];                // coalesced (x fast)
        float t = tg[(y0 + r) * HW + x];
        float e = (p - t) * (p - t);
        acc += (double)e * (double)dv;
    }
    if (!fg) acc = 0.0;              // empty-foreground image contributes 0

    // Block reduction: warp shuffles, then smem (reused) for 32 warp sums.
    #pragma unroll
    for (int o = 16; o > 0; o >>= 1)
        acc += __shfl_down_sync(0xFFFFFFFFu, acc, o);

    __syncthreads();                 // done reading s; safe to reuse
    double* ws = (double*)s;
    int wid = tid >> 5, lane = tid & 31;
    if (lane == 0) ws[wid] = acc;
    __syncthreads();

    if (wid == 0) {
        double v = ws[lane];
        #pragma unroll
        for (int o = 16; o > 0; o >>= 1)
            v += __shfl_down_sync(0xFFFFFFFFu, v, o);
        if (lane == 0) {
            atomicAdd(&g_accum, v);
            __threadfence();
            unsigned done = atomicAdd(&g_counter, 1u);
            if (done == gridDim.x - 1) {
                double tot = atomicAdd(&g_accum, 0.0);     // coherent read
                out[0] = (float)(tot * (1.0 / (double)TOTAL));
                // Self-reset device state for the next graph replay.
                g_accum = 0.0;
                g_counter = 0u;
                #pragma unroll
                for (int i = 0; i < 8; ++i) g_fgany[i] = 0;
            }
        }
    }
}

extern "C" void kernel_launch(void* const* d_in, const int* in_sizes, int n_in,
                              void* d_out, int out_size) {
    const float* pred   = (const float*)d_in[0];
    const float* target = (const float*)d_in[1];
    float* out = (float*)d_out;

    stage1_kernel<<<256, 1024>>>(pred, target);
    stage2_kernel<<<256, 1024>>>(pred, target, out);
}

// round 5
// speedup vs baseline: 1.4307x; 1.0524x over previous
#include <cuda_runtime.h>

// HausdorffDTLoss, [4,1,256,256] fp32 inputs.
// loss = mean( (pred-target)^2 * (pred_dt^2 + target_dt^2) )
// dt^2 = min(F_fg,BIG) + min(F_~fg,BIG)  (exactly one EDT is 0 per pixel),
// F = separable 1D min-plus squared-distance transform (y-pass then x-pass).
// Each 1D transform: outward windowed scan, per-lane early exit, 4 arrays
// per thread scanned CONCURRENTLY (ILP-4; loop count = max of 4 windows).
// Bit-exact vs brute force: every candidate is the identical fp32 expression
// f[j] + (i-j)^2 and f >= 0, so candidates with d^2 >= current-min never win.

#define BIGF 1e10f
#define HW 256
#define IMG 65536
#define TOTAL 262144
#define ARR 766          // array stride in floats (766 % 32 = 30 -> distinct banks)
#define OFF 255          // data starts at 255 (255 pads left and right)

// Vertical-pass output, layout [in(2)][b(4)][mask(2)][x][y] (transposed)
__device__ float g_P1[2 * 4 * 2 * IMG];
__device__ int g_fgany[8];          // [in*4 + b]; zero-init, self-reset
__device__ double g_accum;          // zero-init, self-reset
__device__ unsigned int g_counter;  // zero-init, self-reset

// Concurrent windowed min-plus over 4 contiguous arrays (stride ARR).
// A points at element 0 of array 0; valid data 0..255 with >=255 pads.
__device__ __forceinline__ void scan4(const float* __restrict__ A, int i,
                                      float r[4])
{
    float m0 = A[i];
    float m1 = A[i + ARR];
    float m2 = A[i + 2 * ARR];
    float m3 = A[i + 3 * ARR];
    float d2 = 1.0f, st = 3.0f;      // d2 = d*d, st = 2d+1 (exact in fp32)
    #pragma unroll 1
    for (int d = 1; d < 256; ++d) {
        float mx = fmaxf(fmaxf(m0, m1), fmaxf(m2, m3));
        if (d2 >= mx) break;         // no farther candidate can win any of the 4
        m0 = fminf(m0, fminf(A[i - d],           A[i + d])           + d2);
        m1 = fminf(m1, fminf(A[i - d + ARR],     A[i + d + ARR])     + d2);
        m2 = fminf(m2, fminf(A[i - d + 2 * ARR], A[i + d + 2 * ARR]) + d2);
        m3 = fminf(m3, fminf(A[i - d + 3 * ARR], A[i + d + 3 * ARR]) + d2);
        d2 += st; st += 2.0f;
    }
    r[0] = m0; r[1] = m1; r[2] = m2; r[3] = m3;
}

// ---------------------------------------------------------------------------
// Stage 1: vertical min-plus (along y). Block = (in, b, 8-column tile).
// 256 blocks x 1024 threads. Arrays a = k*2 + mask (k = col 0..7).
// Thread (q = tid>>8, y = tid&255) scans arrays 4q..4q+3 = cols 2q,2q+1.
// Output transposed [x][y] so stage-2 loads are coalesced.
// ---------------------------------------------------------------------------
__global__ __launch_bounds__(1024, 2) void stage1_kernel(
    const float* __restrict__ pred, const float* __restrict__ target)
{
    __shared__ __align__(16) float s[16 * ARR];   // 49024 B

    int bid = blockIdx.x;            // 0..255
    int xt  = bid & 31;
    int b   = (bid >> 5) & 3;
    int in  = bid >> 7;
    int x0  = xt * 8;
    int tid = threadIdx.x;

    // Fill all with BIG (covers pads), then overwrite the data region.
    #pragma unroll
    for (int it = 0; it < 12; ++it) {
        int idx = it * 1024 + tid;
        if (idx < 16 * ARR) s[idx] = BIGF;
    }
    __syncthreads();

    const float* img = (in == 0 ? pred : target) + b * IMG;

    int anyfg = 0;
    #pragma unroll
    for (int it = 0; it < 2; ++it) {
        int idx = it * 1024 + tid;
        int j = idx >> 3;            // y
        int k = idx & 7;             // column within tile
        float v = img[j * HW + x0 + k];        // coalesced
        bool fg = v > 0.5f;
        anyfg |= (int)fg;
        s[(k * 2 + 0) * ARR + OFF + j] = fg ? BIGF : 0.0f;
        s[(k * 2 + 1) * ARR + OFF + j] = fg ? 0.0f : BIGF;
    }
    int blk_any = __syncthreads_or(anyfg);
    if (tid == 0 && blk_any) atomicOr(&g_fgany[in * 4 + b], 1);

    int q = tid >> 8;                // 0..3  -> cols 2q, 2q+1, both masks
    int y = tid & 255;
    float res[4];
    scan4(s + (4 * q) * ARR + OFF, y, res);

    // res: [col 2q,m0][col 2q,m1][col 2q+1,m0][col 2q+1,m1]
    int base = ((in * 4 + b) * 2) * IMG;
    int k0 = x0 + 2 * q;
    g_P1[base + 0 * IMG + (k0 + 0) * HW + y] = res[0];   // coalesced (y fast)
    g_P1[base + 1 * IMG + (k0 + 0) * HW + y] = res[1];
    g_P1[base + 0 * IMG + (k0 + 1) * HW + y] = res[2];
    g_P1[base + 1 * IMG + (k0 + 1) * HW + y] = res[3];
}

// ---------------------------------------------------------------------------
// Stage 2: horizontal min-plus + per-image loss + reduction + finalize.
// Block = (in, b, 8-row tile). Arrays a = r*2 + mask (r = row 0..7).
// Thread (q, x) scans arrays 4q..4q+3 = rows 2q,2q+1 both masks -> combines
// dv in-register (no smem writeback phase).
// ---------------------------------------------------------------------------
__global__ __launch_bounds__(1024, 2) void stage2_kernel(
    const float* __restrict__ pred, const float* __restrict__ target,
    float* __restrict__ out)
{
    __shared__ __align__(16) float s[16 * ARR];

    int bid = blockIdx.x;
    int yt  = bid & 31;
    int b   = (bid >> 5) & 3;
    int in  = bid >> 7;
    int y0  = yt * 8;
    int tid = threadIdx.x;

    #pragma unroll
    for (int it = 0; it < 12; ++it) {
        int idx = it * 1024 + tid;
        if (idx < 16 * ARR) s[idx] = BIGF;
    }
    __syncthreads();

    // Load 2 masks x 8 rows x 256 x from transposed P1 (coalesced: r fast).
    const float* P0 = g_P1 + ((in * 4 + b) * 2) * IMG;   // [x][y] layout
    #pragma unroll
    for (int mm = 0; mm < 2; ++mm) {
        const float* P = P0 + mm * IMG;
        #pragma unroll
        for (int it = 0; it < 2; ++it) {
            int idx = it * 1024 + tid;
            int x = idx >> 3;        // x
            int r = idx & 7;         // row within tile
            s[(r * 2 + mm) * ARR + OFF + x] = P[x * HW + y0 + r];
        }
    }
    __syncthreads();

    int q = tid >> 8;                // rows 2q, 2q+1
    int x = tid & 255;
    float res[4];
    scan4(s + (4 * q) * ARR + OFF, x, res);

    int fg = g_fgany[in * 4 + b];
    const float* pr = pred + b * IMG;
    const float* tg = target + b * IMG;

    // dv = this image's squared distance field (cross term exactly 0)
    float dv0 = fminf(res[0], BIGF) + fminf(res[1], BIGF);   // row 2q
    float dv1 = fminf(res[2], BIGF) + fminf(res[3], BIGF);   // row 2q+1
    int i0 = (y0 + 2 * q) * HW + x;
    int i1 = i0 + HW;
    float e0 = pr[i0] - tg[i0]; e0 *= e0;
    float e1 = pr[i1] - tg[i1]; e1 *= e1;
    double acc = (double)e0 * (double)dv0 + (double)e1 * (double)dv1;
    if (!fg) acc = 0.0;              // empty-foreground image contributes 0

    // Block reduction: warp shuffles, then smem (reused) for 32 warp sums.
    #pragma unroll
    for (int o = 16; o > 0; o >>= 1)
        acc += __shfl_down_sync(0xFFFFFFFFu, acc, o);

    __syncthreads();                 // done reading s; safe to reuse
    double* ws = (double*)s;
    int wid = tid >> 5, lane = tid & 31;
    if (lane == 0) ws[wid] = acc;
    __syncthreads();

    if (wid == 0) {
        double v = ws[lane];
        #pragma unroll
        for (int o = 16; o > 0; o >>= 1)
            v += __shfl_down_sync(0xFFFFFFFFu, v, o);
        if (lane == 0) {
            atomicAdd(&g_accum, v);
            __threadfence();
            unsigned done = atomicAdd(&g_counter, 1u);
            if (done == gridDim.x - 1) {
                double tot = atomicAdd(&g_accum, 0.0);     // coherent read
                out[0] = (float)(tot * (1.0 / (double)TOTAL));
                // Self-reset device state for the next graph replay.
                g_accum = 0.0;
                g_counter = 0u;
                #pragma unroll
                for (int i = 0; i < 8; ++i) g_fgany[i] = 0;
            }
        }
    }
}

extern "C" void kernel_launch(void* const* d_in, const int* in_sizes, int n_in,
                              void* d_out, int out_size) {
    const float* pred   = (const float*)d_in[0];
    const float* target = (const float*)d_in[1];
    float* out = (float*)d_out;

    stage1_kernel<<<256, 1024>>>(pred, target);
    stage2_kernel<<<256, 1024>>>(pred, target, out);
}